// round 1
// baseline (speedup 1.0000x reference)
#include <cuda_runtime.h>
#include <cuda_bf16.h>

#define MM    8192
#define BSZ   16
#define HID   32
#define WIN   64
#define NNZ   131072
#define FW    512          // BSZ*HID features per node-row
#define NKCH  512          // fc1 split-K chunks
#define MPC   16           // m-rows per fc1 chunk (MM/NKCH)
#define KTOT  262144       // MM*HID

// ---------------- scratch (static device globals; no runtime alloc) -------
__device__ int   g_count[MM];
__device__ int   g_rowstart[MM + 1];
__device__ int   g_cursor[MM];
__device__ int   g_scol[NNZ];
__device__ float g_sval[NNZ];
__device__ float g_bufA[MM * FW];          // 16 MB
__device__ float g_bufB[MM * FW];          // 16 MB
__device__ float g_stats[MM * 64];         // per-row [sum(32), sumsq(32)]
__device__ float g_stats2[64 * 64];
__device__ float g_bn[64];                 // scale[32], shift[32]
__device__ float g_part[NKCH * BSZ * FW];  // 16 MB fc1 split-K partials

// ---------------- f32x2 packed-FMA helpers (sm_103a) ----------------------
#define FMA2(d, a, b, c) asm("fma.rn.f32x2 %0, %1, %2, %3;" \
    : "=l"(d) : "l"(a), "l"(b), "l"(c))
#define PACKD(d, lo, hi) asm("mov.b64 %0, {%1, %2};" \
    : "=l"(d) : "f"(lo), "f"(hi))
#define UNPACKD(lo, hi, d) asm("mov.b64 {%0, %1}, %2;" \
    : "=f"(lo), "=f"(hi) : "l"(d))

// ================= CSR build ==============================================
__global__ void k_zero() {
    int i = blockIdx.x * blockDim.x + threadIdx.x;
    if (i < MM) g_count[i] = 0;
}

__global__ void k_hist(const int* __restrict__ row) {
    int e = blockIdx.x * blockDim.x + threadIdx.x;
    if (e < NNZ) atomicAdd(&g_count[row[e]], 1);
}

__global__ void k_scan() {  // 1 block, 1024 threads, 8 rows each
    __shared__ int sm[1024];
    int t = threadIdx.x;
    int loc[8];
    int s = 0;
#pragma unroll
    for (int i = 0; i < 8; i++) { loc[i] = g_count[t * 8 + i]; s += loc[i]; }
    sm[t] = s;
    __syncthreads();
    for (int off = 1; off < 1024; off <<= 1) {
        int v = (t >= off) ? sm[t - off] : 0;
        __syncthreads();
        sm[t] += v;
        __syncthreads();
    }
    int run = (t == 0) ? 0 : sm[t - 1];
#pragma unroll
    for (int i = 0; i < 8; i++) {
        g_rowstart[t * 8 + i] = run;
        g_cursor[t * 8 + i] = run;
        run += loc[i];
    }
    if (t == 1023) g_rowstart[MM] = run;
}

__global__ void k_scatter(const int* __restrict__ row, const int* __restrict__ col,
                          const float* __restrict__ val) {
    int e = blockIdx.x * blockDim.x + threadIdx.x;
    if (e < NNZ) {
        int r = row[e];
        int p = atomicAdd(&g_cursor[r], 1);
        g_scol[p] = col[e];
        g_sval[p] = val[e];
    }
}

// ================= layer-1 linear: t1[(m,b),:] = inputs[b,m,:] @ W1 =======
__global__ void k_lin1(const float* __restrict__ x, const float* __restrict__ W) {
    __shared__ __align__(16) float w[WIN * HID];   // 8 KB
    for (int i = threadIdx.x; i < WIN * HID; i += blockDim.x) w[i] = W[i];
    __syncthreads();
    int tid = blockIdx.x * 256 + threadIdx.x;      // tid = b*MM + m
    int b = tid >> 13;
    int m = tid & (MM - 1);
    const float4* xr = (const float4*)(x + ((size_t)b * MM + m) * WIN);
    float acc[HID];
#pragma unroll
    for (int c = 0; c < HID; c++) acc[c] = 0.f;
#pragma unroll
    for (int f4 = 0; f4 < WIN / 4; f4++) {
        float4 xv = xr[f4];
#pragma unroll
        for (int k = 0; k < 4; k++) {
            float xe = (k == 0) ? xv.x : (k == 1) ? xv.y : (k == 2) ? xv.z : xv.w;
            const float4* wr = (const float4*)(w + (f4 * 4 + k) * HID);
#pragma unroll
            for (int c4 = 0; c4 < HID / 4; c4++) {
                float4 wv = wr[c4];
                acc[c4 * 4 + 0] += xe * wv.x;
                acc[c4 * 4 + 1] += xe * wv.y;
                acc[c4 * 4 + 2] += xe * wv.z;
                acc[c4 * 4 + 3] += xe * wv.w;
            }
        }
    }
    float4* out = (float4*)(g_bufA + ((size_t)m * BSZ + b) * HID);
#pragma unroll
    for (int c4 = 0; c4 < HID / 4; c4++) {
        float4 o = {acc[c4 * 4 + 0], acc[c4 * 4 + 1], acc[c4 * 4 + 2], acc[c4 * 4 + 3]};
        out[c4] = o;
    }
}

// ================= SpMM: y[r,:] = sum_e val*x[col,:] + bias; + BN partials =
__global__ void k_spmm(const float* __restrict__ x, const float* __restrict__ bias,
                       float* __restrict__ y) {
    int r = blockIdx.x;
    int t = threadIdx.x;                 // 128 threads, 4 features each
    __shared__ int   scol[128];
    __shared__ float sval[128];
    __shared__ float4 ssum[128];
    __shared__ float4 ssq[128];
    int s = g_rowstart[r], e = g_rowstart[r + 1];
    float4 acc = {0.f, 0.f, 0.f, 0.f};
    for (int base = s; base < e; base += 128) {
        int n = min(128, e - base);
        __syncthreads();
        if (t < n) { scol[t] = g_scol[base + t]; sval[t] = g_sval[base + t]; }
        __syncthreads();
        for (int i = 0; i < n; i++) {
            float v = sval[i];
            float4 xv = *(const float4*)(x + (size_t)scol[i] * FW + t * 4);
            acc.x += v * xv.x; acc.y += v * xv.y;
            acc.z += v * xv.z; acc.w += v * xv.w;
        }
    }
    int c0 = (t & 7) * 4;                // channel base (feature = b*32+c)
    float4 bv = *(const float4*)(bias + c0);
    acc.x += bv.x; acc.y += bv.y; acc.z += bv.z; acc.w += bv.w;
    *(float4*)(y + (size_t)r * FW + t * 4) = acc;
    ssum[t] = acc;
    float4 sq = {acc.x * acc.x, acc.y * acc.y, acc.z * acc.z, acc.w * acc.w};
    ssq[t] = sq;
    __syncthreads();
    if (t < 8) {                         // deterministic reduce over 16 b
        float4 a = {0, 0, 0, 0}, q = {0, 0, 0, 0};
        for (int k = 0; k < 16; k++) {
            float4 u = ssum[k * 8 + t], v = ssq[k * 8 + t];
            a.x += u.x; a.y += u.y; a.z += u.z; a.w += u.w;
            q.x += v.x; q.y += v.y; q.z += v.z; q.w += v.w;
        }
        *(float4*)(g_stats + (size_t)r * 64 + t * 4) = a;
        *(float4*)(g_stats + (size_t)r * 64 + 32 + t * 4) = q;
    }
}

// ================= BN reductions ==========================================
__global__ void k_bnred() {              // grid 64, 256 threads
    int bx = blockIdx.x, t = threadIdx.x;
    int col = t & 63, seg = t >> 6;      // 4 segments x 32 rows
    float s = 0.f;
    int r0 = bx * 128 + seg * 32;
    for (int i = 0; i < 32; i++) s += g_stats[(size_t)(r0 + i) * 64 + col];
    __shared__ float sm[256];
    sm[t] = s;
    __syncthreads();
    if (seg == 0)
        g_stats2[bx * 64 + col] = sm[col] + sm[64 + col] + sm[128 + col] + sm[192 + col];
}

__global__ void k_bnfin(const float* __restrict__ g, const float* __restrict__ be) {
    int t = threadIdx.x;                 // 64 threads
    float s = 0.f;
    for (int i = 0; i < 64; i++) s += g_stats2[i * 64 + t];
    __shared__ float sm[64];
    sm[t] = s;
    __syncthreads();
    if (t < 32) {
        const float inv_n = 1.f / (float)(BSZ * MM);
        float mean = sm[t] * inv_n;
        float var = sm[32 + t] * inv_n - mean * mean;
        float sc = g[t] * rsqrtf(var + 1e-5f);
        g_bn[t] = sc;
        g_bn[32 + t] = be[t] - mean * sc;
    }
}

// ================= layer-2 linear with fused BN+ReLU on input =============
__global__ void k_lin2(const float* __restrict__ y, const float* __restrict__ W,
                       float* __restrict__ out) {
    __shared__ __align__(16) float w[HID * HID];
    __shared__ float sc[32], sh[32];
    for (int i = threadIdx.x; i < HID * HID; i += blockDim.x) w[i] = W[i];
    if (threadIdx.x < 32) { sc[threadIdx.x] = g_bn[threadIdx.x]; sh[threadIdx.x] = g_bn[32 + threadIdx.x]; }
    __syncthreads();
    int tid = blockIdx.x * 256 + threadIdx.x;   // tid = m*16+b row index
    const float4* yr = (const float4*)(y + (size_t)tid * HID);
    float xv[HID];
#pragma unroll
    for (int c4 = 0; c4 < HID / 4; c4++) {
        float4 v = yr[c4];
        xv[c4 * 4 + 0] = fmaxf(sc[c4 * 4 + 0] * v.x + sh[c4 * 4 + 0], 0.f);
        xv[c4 * 4 + 1] = fmaxf(sc[c4 * 4 + 1] * v.y + sh[c4 * 4 + 1], 0.f);
        xv[c4 * 4 + 2] = fmaxf(sc[c4 * 4 + 2] * v.z + sh[c4 * 4 + 2], 0.f);
        xv[c4 * 4 + 3] = fmaxf(sc[c4 * 4 + 3] * v.w + sh[c4 * 4 + 3], 0.f);
    }
    float acc[HID];
#pragma unroll
    for (int d = 0; d < HID; d++) acc[d] = 0.f;
#pragma unroll
    for (int c = 0; c < HID; c++) {
        float xe = xv[c];
        const float4* wr = (const float4*)(w + c * HID);
#pragma unroll
        for (int d4 = 0; d4 < HID / 4; d4++) {
            float4 wv = wr[d4];
            acc[d4 * 4 + 0] += xe * wv.x;
            acc[d4 * 4 + 1] += xe * wv.y;
            acc[d4 * 4 + 2] += xe * wv.z;
            acc[d4 * 4 + 3] += xe * wv.w;
        }
    }
    float4* o = (float4*)(out + (size_t)tid * HID);
#pragma unroll
    for (int d4 = 0; d4 < HID / 4; d4++) {
        float4 v = {acc[d4 * 4 + 0], acc[d4 * 4 + 1], acc[d4 * 4 + 2], acc[d4 * 4 + 3]};
        o[d4] = v;
    }
}

// ================= fc1 split-K GEMM with f32x2 and fused BN+ReLU ==========
__global__ void __launch_bounds__(128) k_fc1(const float* __restrict__ w,
                                             const float* __restrict__ y2) {
    int ck = blockIdx.x;                  // K-chunk: m in [ck*16, ck*16+16)
    int t = threadIdx.x;                  // thread owns 4 j-cols, all 16 b
    __shared__ __align__(16) float xs[FW];  // transposed tile xs[c*16 + b]
    __shared__ float sc[32], sh[32];
    if (t < 32) { sc[t] = g_bn[t]; sh[t] = g_bn[32 + t]; }
    unsigned long long acc[32];           // [b2(8)][j(4)], packed b-pairs
#pragma unroll
    for (int i = 0; i < 32; i++) acc[i] = 0ULL;
    int j0 = t * 4;
    for (int mi = 0; mi < MPC; mi++) {
        int m = ck * MPC + mi;
        __syncthreads();
        {   // stage + BN + ReLU + transpose to xs[c*16+b]
            float4 v = ((const float4*)(y2 + (size_t)m * FW))[t];
            int b = t >> 3;
            int c = (t & 7) * 4;
            xs[(c + 0) * 16 + b] = fmaxf(sc[c + 0] * v.x + sh[c + 0], 0.f);
            xs[(c + 1) * 16 + b] = fmaxf(sc[c + 1] * v.y + sh[c + 1], 0.f);
            xs[(c + 2) * 16 + b] = fmaxf(sc[c + 2] * v.z + sh[c + 2], 0.f);
            xs[(c + 3) * 16 + b] = fmaxf(sc[c + 3] * v.w + sh[c + 3], 0.f);
        }
        __syncthreads();
        const float* wrow = w + (size_t)m * HID * FW + j0;
#pragma unroll 4
        for (int c = 0; c < HID; c++) {
            float4 wv = *(const float4*)(wrow + (size_t)c * FW);
            unsigned long long w2x, w2y, w2z, w2w;
            PACKD(w2x, wv.x, wv.x); PACKD(w2y, wv.y, wv.y);
            PACKD(w2z, wv.z, wv.z); PACKD(w2w, wv.w, wv.w);
            const ulonglong2* xp = (const ulonglong2*)(xs + c * 16);
#pragma unroll
            for (int q = 0; q < 4; q++) {
                ulonglong2 xv = xp[q];      // b-pairs (2q, 2q+1)
                FMA2(acc[(2 * q + 0) * 4 + 0], xv.x, w2x, acc[(2 * q + 0) * 4 + 0]);
                FMA2(acc[(2 * q + 0) * 4 + 1], xv.x, w2y, acc[(2 * q + 0) * 4 + 1]);
                FMA2(acc[(2 * q + 0) * 4 + 2], xv.x, w2z, acc[(2 * q + 0) * 4 + 2]);
                FMA2(acc[(2 * q + 0) * 4 + 3], xv.x, w2w, acc[(2 * q + 0) * 4 + 3]);
                FMA2(acc[(2 * q + 1) * 4 + 0], xv.y, w2x, acc[(2 * q + 1) * 4 + 0]);
                FMA2(acc[(2 * q + 1) * 4 + 1], xv.y, w2y, acc[(2 * q + 1) * 4 + 1]);
                FMA2(acc[(2 * q + 1) * 4 + 2], xv.y, w2z, acc[(2 * q + 1) * 4 + 2]);
                FMA2(acc[(2 * q + 1) * 4 + 3], xv.y, w2w, acc[(2 * q + 1) * 4 + 3]);
            }
        }
    }
    float* pbase = g_part + (size_t)ck * BSZ * FW;
#pragma unroll
    for (int b2 = 0; b2 < 8; b2++) {
        float lo0, hi0, lo1, hi1, lo2, hi2, lo3, hi3;
        UNPACKD(lo0, hi0, acc[b2 * 4 + 0]);
        UNPACKD(lo1, hi1, acc[b2 * 4 + 1]);
        UNPACKD(lo2, hi2, acc[b2 * 4 + 2]);
        UNPACKD(lo3, hi3, acc[b2 * 4 + 3]);
        float4 e = {lo0, lo1, lo2, lo3};
        float4 o = {hi0, hi1, hi2, hi3};
        *(float4*)(pbase + (size_t)(2 * b2 + 0) * FW + j0) = e;
        *(float4*)(pbase + (size_t)(2 * b2 + 1) * FW + j0) = o;
    }
}

// ================= reduce partials + extras + bias + relu + fc2 ===========
__global__ void k_red(const float* __restrict__ w, const float* __restrict__ fc1b,
                      const float* __restrict__ ex, const float* __restrict__ fc2w,
                      const float* __restrict__ fc2b, float* __restrict__ out) {
    int b = blockIdx.x;                  // 16 blocks
    int j = threadIdx.x;                 // 512 threads
    const float* p = g_part + (size_t)b * FW + j;
    float a0 = 0.f, a1 = 0.f, a2 = 0.f, a3 = 0.f;
    for (int ck = 0; ck < NKCH; ck += 4) {
        a0 += p[(size_t)(ck + 0) * BSZ * FW];
        a1 += p[(size_t)(ck + 1) * BSZ * FW];
        a2 += p[(size_t)(ck + 2) * BSZ * FW];
        a3 += p[(size_t)(ck + 3) * BSZ * FW];
    }
    float acc = (a0 + a1) + (a2 + a3) + fc1b[j];
#pragma unroll
    for (int e2 = 0; e2 < 32; e2++)
        acc += ex[b * 32 + e2] * w[((size_t)KTOT + e2) * FW + j];
    float h = fmaxf(acc, 0.f);
    __shared__ float r0[512], r1[512];
    r0[j] = h * fc2w[j * 2 + 0];
    r1[j] = h * fc2w[j * 2 + 1];
    __syncthreads();
    for (int s = 256; s > 0; s >>= 1) {
        if (j < s) { r0[j] += r0[j + s]; r1[j] += r1[j + s]; }
        __syncthreads();
    }
    if (j == 0) {
        out[b * 2 + 0] = r0[0] + fc2b[0];
        out[b * 2 + 1] = r1[0] + fc2b[1];
    }
}

// ================= launch ==================================================
extern "C" void kernel_launch(void* const* d_in, const int* in_sizes, int n_in,
                              void* d_out, int out_size) {
    const float* inputs  = (const float*)d_in[0];
    const float* ex      = (const float*)d_in[1];
    const int*   erow    = (const int*)  d_in[2];
    const int*   ecol    = (const int*)  d_in[3];
    const float* eval    = (const float*)d_in[4];
    const float* W1      = (const float*)d_in[5];
    const float* b1      = (const float*)d_in[6];
    const float* g1      = (const float*)d_in[7];
    const float* be1     = (const float*)d_in[8];
    const float* W2      = (const float*)d_in[9];
    const float* b2      = (const float*)d_in[10];
    const float* g2      = (const float*)d_in[11];
    const float* be2     = (const float*)d_in[12];
    const float* fc1w    = (const float*)d_in[13];
    const float* fc1b    = (const float*)d_in[14];
    const float* fc2w    = (const float*)d_in[15];
    const float* fc2b    = (const float*)d_in[16];
    float* out = (float*)d_out;

    float* bufA; cudaGetSymbolAddress((void**)&bufA, g_bufA);
    float* bufB; cudaGetSymbolAddress((void**)&bufB, g_bufB);

    k_zero<<<8, 1024>>>();
    k_hist<<<NNZ / 256, 256>>>(erow);
    k_scan<<<1, 1024>>>();
    k_scatter<<<NNZ / 256, 256>>>(erow, ecol, eval);

    k_lin1<<<(BSZ * MM) / 256, 256>>>(inputs, W1);         // bufA = X@W1   (m,b,c)
    k_spmm<<<MM, 128>>>(bufA, b1, bufB);                    // bufB = L@bufA + b1, stats
    k_bnred<<<64, 256>>>();
    k_bnfin<<<1, 64>>>(g1, be1);
    k_lin2<<<(BSZ * MM) / 256, 256>>>(bufB, W2, bufA);      // bufA = bnrelu(bufB)@W2
    k_spmm<<<MM, 128>>>(bufA, b2, bufB);                    // bufB = L@bufA + b2, stats
    k_bnred<<<64, 256>>>();
    k_bnfin<<<1, 64>>>(g2, be2);

    k_fc1<<<NKCH, 128>>>(fc1w, bufB);                       // split-K partials
    k_red<<<BSZ, 512>>>(fc1w, fc1b, ex, fc2w, fc2b, out);   // reduce + fc2
}

// round 2
// speedup vs baseline: 1.0984x; 1.0984x over previous
#include <cuda_runtime.h>
#include <cuda_bf16.h>

#define MM    8192
#define BSZ   16
#define HID   32
#define WIN   64
#define NNZ   131072
#define FW    512          // BSZ*HID features per node-row
#define NKCH  512          // fc1 split-K chunks
#define MPC   16           // m-rows per fc1 chunk (MM/NKCH)
#define KTOT  262144       // MM*HID

// ---------------- scratch (static device globals; no runtime alloc) -------
__device__ int   g_count[MM];
__device__ int   g_rowstart[MM + 1];
__device__ int   g_cursor[MM];
__device__ unsigned long long g_ecv[NNZ];   // packed (val<<32 | col)
__device__ float g_bufA[MM * FW];           // 16 MB
__device__ float g_bufB[MM * FW];           // 16 MB
__device__ float g_stats[MM * 64];          // per-row [sum(32), sumsq(32)]
__device__ float g_stats2[64 * 64];
__device__ float g_bn[64];                  // scale[32], shift[32]
__device__ int   g_bnticket;
__device__ float g_part[NKCH * BSZ * FW];   // 16 MB fc1 split-K partials
__device__ float g_red[BSZ * 8 * FW];       // stage-1 reduced partials

// ---------------- f32x2 packed-FMA helpers (sm_103a) ----------------------
#define FMA2(d, a, b, c) asm("fma.rn.f32x2 %0, %1, %2, %3;" \
    : "=l"(d) : "l"(a), "l"(b), "l"(c))
#define PACKD(d, lo, hi) asm("mov.b64 %0, {%1, %2};" \
    : "=l"(d) : "f"(lo), "f"(hi))
#define UNPACKD(lo, hi, d) asm("mov.b64 {%0, %1}, %2;" \
    : "=f"(lo), "=f"(hi) : "l"(d))

// ================= CSR build ==============================================
__global__ void k_hist(const int* __restrict__ row) {
    int e = blockIdx.x * blockDim.x + threadIdx.x;
    if (e < NNZ) atomicAdd(&g_count[row[e]], 1);
}

__global__ void k_scan() {  // 1 block, 1024 threads, 8 rows each
    __shared__ int sm[1024];
    int t = threadIdx.x;
    int loc[8];
    int s = 0;
#pragma unroll
    for (int i = 0; i < 8; i++) { loc[i] = g_count[t * 8 + i]; s += loc[i]; }
    sm[t] = s;
    __syncthreads();
    for (int off = 1; off < 1024; off <<= 1) {
        int v = (t >= off) ? sm[t - off] : 0;
        __syncthreads();
        sm[t] += v;
        __syncthreads();
    }
    int run = (t == 0) ? 0 : sm[t - 1];
#pragma unroll
    for (int i = 0; i < 8; i++) {
        g_rowstart[t * 8 + i] = run;
        g_cursor[t * 8 + i] = run;
        run += loc[i];
    }
    if (t == 1023) g_rowstart[MM] = run;
}

__global__ void k_scatter(const int* __restrict__ row, const int* __restrict__ col,
                          const float* __restrict__ val) {
    int e = blockIdx.x * blockDim.x + threadIdx.x;
    if (e < NNZ) {
        int r = row[e];
        unsigned long long pk =
            ((unsigned long long)__float_as_uint(val[e]) << 32) | (unsigned)col[e];
        int p = atomicAdd(&g_cursor[r], 1);
        g_ecv[p] = pk;
    }
}

// ================= layer-1 linear: t1[(m,b),:] = inputs[b,m,:] @ W1 =======
__global__ void k_lin1(const float* __restrict__ x, const float* __restrict__ W) {
    __shared__ __align__(16) float w[WIN * HID];   // 8 KB
    for (int i = threadIdx.x; i < WIN * HID; i += blockDim.x) w[i] = W[i];
    __syncthreads();
    int tid = blockIdx.x * 256 + threadIdx.x;      // tid = b*MM + m
    int b = tid >> 13;
    int m = tid & (MM - 1);
    const float4* xr = (const float4*)(x + ((size_t)b * MM + m) * WIN);
    float acc[HID];
#pragma unroll
    for (int c = 0; c < HID; c++) acc[c] = 0.f;
#pragma unroll
    for (int f4 = 0; f4 < WIN / 4; f4++) {
        float4 xv = xr[f4];
#pragma unroll
        for (int k = 0; k < 4; k++) {
            float xe = (k == 0) ? xv.x : (k == 1) ? xv.y : (k == 2) ? xv.z : xv.w;
            const float4* wr = (const float4*)(w + (f4 * 4 + k) * HID);
#pragma unroll
            for (int c4 = 0; c4 < HID / 4; c4++) {
                float4 wv = wr[c4];
                acc[c4 * 4 + 0] += xe * wv.x;
                acc[c4 * 4 + 1] += xe * wv.y;
                acc[c4 * 4 + 2] += xe * wv.z;
                acc[c4 * 4 + 3] += xe * wv.w;
            }
        }
    }
    float4* out = (float4*)(g_bufA + ((size_t)m * BSZ + b) * HID);
#pragma unroll
    for (int c4 = 0; c4 < HID / 4; c4++) {
        float4 o = {acc[c4 * 4 + 0], acc[c4 * 4 + 1], acc[c4 * 4 + 2], acc[c4 * 4 + 3]};
        out[c4] = o;
    }
}

// ================= SpMM: y[r,:] = sum_e val*x[col,:] + bias; + BN partials =
__global__ void k_spmm(const float* __restrict__ x, const float* __restrict__ bias,
                       float* __restrict__ y) {
    int r = blockIdx.x;
    int t = threadIdx.x;                 // 128 threads, 4 features each
    __shared__ unsigned long long ecv[128];
    __shared__ float4 ssum[128];
    __shared__ float4 ssq[128];
    int s = g_rowstart[r], e = g_rowstart[r + 1];
    int t4 = t * 4;
    float4 a0 = {0,0,0,0}, a1 = {0,0,0,0}, a2 = {0,0,0,0}, a3 = {0,0,0,0};
    for (int base = s; base < e; base += 128) {
        int n = min(128, e - base);
        __syncthreads();
        if (t < n) ecv[t] = g_ecv[base + t];
        __syncthreads();
        int i = 0;
        for (; i + 4 <= n; i += 4) {
            unsigned long long u0 = ecv[i], u1 = ecv[i+1], u2 = ecv[i+2], u3 = ecv[i+3];
            float v0 = __uint_as_float((unsigned)(u0 >> 32));
            float v1 = __uint_as_float((unsigned)(u1 >> 32));
            float v2 = __uint_as_float((unsigned)(u2 >> 32));
            float v3 = __uint_as_float((unsigned)(u3 >> 32));
            float4 x0 = *(const float4*)(x + (size_t)(unsigned)(u0 & 0xffffffffu) * FW + t4);
            float4 x1 = *(const float4*)(x + (size_t)(unsigned)(u1 & 0xffffffffu) * FW + t4);
            float4 x2 = *(const float4*)(x + (size_t)(unsigned)(u2 & 0xffffffffu) * FW + t4);
            float4 x3 = *(const float4*)(x + (size_t)(unsigned)(u3 & 0xffffffffu) * FW + t4);
            a0.x += v0 * x0.x; a0.y += v0 * x0.y; a0.z += v0 * x0.z; a0.w += v0 * x0.w;
            a1.x += v1 * x1.x; a1.y += v1 * x1.y; a1.z += v1 * x1.z; a1.w += v1 * x1.w;
            a2.x += v2 * x2.x; a2.y += v2 * x2.y; a2.z += v2 * x2.z; a2.w += v2 * x2.w;
            a3.x += v3 * x3.x; a3.y += v3 * x3.y; a3.z += v3 * x3.z; a3.w += v3 * x3.w;
        }
        for (; i < n; i++) {
            unsigned long long u = ecv[i];
            float v = __uint_as_float((unsigned)(u >> 32));
            float4 xv = *(const float4*)(x + (size_t)(unsigned)(u & 0xffffffffu) * FW + t4);
            a0.x += v * xv.x; a0.y += v * xv.y; a0.z += v * xv.z; a0.w += v * xv.w;
        }
    }
    float4 acc;
    acc.x = (a0.x + a1.x) + (a2.x + a3.x);
    acc.y = (a0.y + a1.y) + (a2.y + a3.y);
    acc.z = (a0.z + a1.z) + (a2.z + a3.z);
    acc.w = (a0.w + a1.w) + (a2.w + a3.w);
    int c0 = (t & 7) * 4;                // channel base (feature = b*32+c)
    float4 bv = *(const float4*)(bias + c0);
    acc.x += bv.x; acc.y += bv.y; acc.z += bv.z; acc.w += bv.w;
    *(float4*)(y + (size_t)r * FW + t4) = acc;
    ssum[t] = acc;
    float4 sq = {acc.x * acc.x, acc.y * acc.y, acc.z * acc.z, acc.w * acc.w};
    ssq[t] = sq;
    __syncthreads();
    if (t < 8) {                         // deterministic reduce over 16 b
        float4 a = {0, 0, 0, 0}, q = {0, 0, 0, 0};
        for (int k = 0; k < 16; k++) {
            float4 u = ssum[k * 8 + t], v = ssq[k * 8 + t];
            a.x += u.x; a.y += u.y; a.z += u.z; a.w += u.w;
            q.x += v.x; q.y += v.y; q.z += v.z; q.w += v.w;
        }
        *(float4*)(g_stats + (size_t)r * 64 + t * 4) = a;
        *(float4*)(g_stats + (size_t)r * 64 + 32 + t * 4) = q;
    }
}

// ================= fused BN reduction (ticket / last-block) ===============
__global__ void k_bn(const float* __restrict__ g, const float* __restrict__ be) {
    int bx = blockIdx.x, t = threadIdx.x;      // grid 64, 256 threads
    int col = t & 63, seg = t >> 6;            // 4 segments x 32 rows
    float s = 0.f;
    int r0 = bx * 128 + seg * 32;
    for (int i = 0; i < 32; i++) s += g_stats[(size_t)(r0 + i) * 64 + col];
    __shared__ float sm[256];
    sm[t] = s;
    __syncthreads();
    if (seg == 0)
        g_stats2[bx * 64 + col] = sm[col] + sm[64 + col] + sm[128 + col] + sm[192 + col];
    __threadfence();
    __shared__ int lastFlag;
    if (t == 0) lastFlag = (atomicAdd(&g_bnticket, 1) == 63);
    __syncthreads();
    if (lastFlag) {
        if (t < 64) {
            float ss = 0.f;
            for (int i = 0; i < 64; i++) ss += g_stats2[i * 64 + t];
            sm[t] = ss;
        }
        __syncthreads();
        if (t < 32) {
            const float inv_n = 1.f / (float)(BSZ * MM);
            float mean = sm[t] * inv_n;
            float var = sm[32 + t] * inv_n - mean * mean;
            float sc = g[t] * rsqrtf(var + 1e-5f);
            g_bn[t] = sc;
            g_bn[32 + t] = be[t] - mean * sc;
        }
        if (t == 0) g_bnticket = 0;   // reset for next use / replay
    }
}

// ================= layer-2 linear with fused BN+ReLU on input =============
__global__ void k_lin2(const float* __restrict__ y, const float* __restrict__ W,
                       float* __restrict__ out) {
    __shared__ __align__(16) float w[HID * HID];
    __shared__ float sc[32], sh[32];
    for (int i = threadIdx.x; i < HID * HID; i += blockDim.x) w[i] = W[i];
    if (threadIdx.x < 32) { sc[threadIdx.x] = g_bn[threadIdx.x]; sh[threadIdx.x] = g_bn[32 + threadIdx.x]; }
    __syncthreads();
    int tid = blockIdx.x * 256 + threadIdx.x;   // tid = m*16+b row index
    const float4* yr = (const float4*)(y + (size_t)tid * HID);
    float xv[HID];
#pragma unroll
    for (int c4 = 0; c4 < HID / 4; c4++) {
        float4 v = yr[c4];
        xv[c4 * 4 + 0] = fmaxf(sc[c4 * 4 + 0] * v.x + sh[c4 * 4 + 0], 0.f);
        xv[c4 * 4 + 1] = fmaxf(sc[c4 * 4 + 1] * v.y + sh[c4 * 4 + 1], 0.f);
        xv[c4 * 4 + 2] = fmaxf(sc[c4 * 4 + 2] * v.z + sh[c4 * 4 + 2], 0.f);
        xv[c4 * 4 + 3] = fmaxf(sc[c4 * 4 + 3] * v.w + sh[c4 * 4 + 3], 0.f);
    }
    float acc[HID];
#pragma unroll
    for (int d = 0; d < HID; d++) acc[d] = 0.f;
#pragma unroll
    for (int c = 0; c < HID; c++) {
        float xe = xv[c];
        const float4* wr = (const float4*)(w + c * HID);
#pragma unroll
        for (int d4 = 0; d4 < HID / 4; d4++) {
            float4 wv = wr[d4];
            acc[d4 * 4 + 0] += xe * wv.x;
            acc[d4 * 4 + 1] += xe * wv.y;
            acc[d4 * 4 + 2] += xe * wv.z;
            acc[d4 * 4 + 3] += xe * wv.w;
        }
    }
    float4* o = (float4*)(out + (size_t)tid * HID);
#pragma unroll
    for (int d4 = 0; d4 < HID / 4; d4++) {
        float4 v = {acc[d4 * 4 + 0], acc[d4 * 4 + 1], acc[d4 * 4 + 2], acc[d4 * 4 + 3]};
        o[d4] = v;
    }
}

// ================= fc1 split-K GEMM with f32x2 and fused BN+ReLU ==========
__global__ void __launch_bounds__(128) k_fc1(const float* __restrict__ w,
                                             const float* __restrict__ y2) {
    int ck = blockIdx.x;                  // K-chunk: m in [ck*16, ck*16+16)
    int t = threadIdx.x;                  // thread owns 4 j-cols, all 16 b
    __shared__ __align__(16) float xs[MPC * FW];   // 32 KB: xs[(mi*32+c)*16 + b]
    __shared__ float sc[32], sh[32];
    if (t < 32) { sc[t] = g_bn[t]; sh[t] = g_bn[32 + t]; }
    __syncthreads();
    // stage all MPC rows once: BN + ReLU + transpose
    {
        int b = t >> 3;
        int c0 = (t & 7) * 4;
        float s0 = sc[c0 + 0], s1 = sc[c0 + 1], s2 = sc[c0 + 2], s3 = sc[c0 + 3];
        float h0 = sh[c0 + 0], h1 = sh[c0 + 1], h2 = sh[c0 + 2], h3 = sh[c0 + 3];
#pragma unroll
        for (int mi = 0; mi < MPC; mi++) {
            float4 v = ((const float4*)(y2 + (size_t)(ck * MPC + mi) * FW))[t];
            float* xr = xs + mi * FW;
            xr[(c0 + 0) * 16 + b] = fmaxf(s0 * v.x + h0, 0.f);
            xr[(c0 + 1) * 16 + b] = fmaxf(s1 * v.y + h1, 0.f);
            xr[(c0 + 2) * 16 + b] = fmaxf(s2 * v.z + h2, 0.f);
            xr[(c0 + 3) * 16 + b] = fmaxf(s3 * v.w + h3, 0.f);
        }
    }
    __syncthreads();
    unsigned long long acc[32];           // [b-pair(8)][j(4)]
#pragma unroll
    for (int i = 0; i < 32; i++) acc[i] = 0ULL;
    int j0 = t * 4;
    const float* wp = w + (size_t)ck * MPC * HID * FW + j0;
#pragma unroll 4
    for (int kc = 0; kc < MPC * HID; kc++) {     // kc = mi*32 + c, streams w
        float4 wv = *(const float4*)(wp + (size_t)kc * FW);
        unsigned long long w2x, w2y, w2z, w2w;
        PACKD(w2x, wv.x, wv.x); PACKD(w2y, wv.y, wv.y);
        PACKD(w2z, wv.z, wv.z); PACKD(w2w, wv.w, wv.w);
        const ulonglong2* xp = (const ulonglong2*)(xs + kc * 16);
#pragma unroll
        for (int q = 0; q < 4; q++) {
            ulonglong2 xv = xp[q];      // b-pairs (2q, 2q+1)
            FMA2(acc[(2 * q + 0) * 4 + 0], xv.x, w2x, acc[(2 * q + 0) * 4 + 0]);
            FMA2(acc[(2 * q + 0) * 4 + 1], xv.x, w2y, acc[(2 * q + 0) * 4 + 1]);
            FMA2(acc[(2 * q + 0) * 4 + 2], xv.x, w2z, acc[(2 * q + 0) * 4 + 2]);
            FMA2(acc[(2 * q + 0) * 4 + 3], xv.x, w2w, acc[(2 * q + 0) * 4 + 3]);
            FMA2(acc[(2 * q + 1) * 4 + 0], xv.y, w2x, acc[(2 * q + 1) * 4 + 0]);
            FMA2(acc[(2 * q + 1) * 4 + 1], xv.y, w2y, acc[(2 * q + 1) * 4 + 1]);
            FMA2(acc[(2 * q + 1) * 4 + 2], xv.y, w2z, acc[(2 * q + 1) * 4 + 2]);
            FMA2(acc[(2 * q + 1) * 4 + 3], xv.y, w2w, acc[(2 * q + 1) * 4 + 3]);
        }
    }
    float* pbase = g_part + (size_t)ck * BSZ * FW;
#pragma unroll
    for (int b2 = 0; b2 < 8; b2++) {
        float lo0, hi0, lo1, hi1, lo2, hi2, lo3, hi3;
        UNPACKD(lo0, hi0, acc[b2 * 4 + 0]);
        UNPACKD(lo1, hi1, acc[b2 * 4 + 1]);
        UNPACKD(lo2, hi2, acc[b2 * 4 + 2]);
        UNPACKD(lo3, hi3, acc[b2 * 4 + 3]);
        float4 ev = {lo0, lo1, lo2, lo3};
        float4 ov = {hi0, hi1, hi2, hi3};
        *(float4*)(pbase + (size_t)(2 * b2 + 0) * FW + j0) = ev;
        *(float4*)(pbase + (size_t)(2 * b2 + 1) * FW + j0) = ov;
    }
}

// ================= reduce partials (stage 1, coalesced float4) ============
__global__ void k_red1() {
    int b = blockIdx.x >> 3;             // 0..15
    int grp = blockIdx.x & 7;            // 0..7, each covers 64 chunks
    int t = threadIdx.x;                 // 128 threads, j-quad each
    const float* p = g_part + (size_t)(grp * 64) * BSZ * FW + (size_t)b * FW + t * 4;
    float4 s = {0, 0, 0, 0};
#pragma unroll 8
    for (int k = 0; k < 64; k++) {
        float4 v = *(const float4*)(p + (size_t)k * BSZ * FW);
        s.x += v.x; s.y += v.y; s.z += v.z; s.w += v.w;
    }
    *(float4*)(g_red + (size_t)(b * 8 + grp) * FW + t * 4) = s;
}

// ================= final: reduce + extras + bias + relu + fc2 =============
__global__ void k_red2(const float* __restrict__ w, const float* __restrict__ fc1b,
                       const float* __restrict__ ex, const float* __restrict__ fc2w,
                       const float* __restrict__ fc2b, float* __restrict__ out) {
    int b = blockIdx.x;                  // 16 blocks
    int j = threadIdx.x;                 // 512 threads
    float acc = fc1b[j];
#pragma unroll
    for (int g = 0; g < 8; g++) acc += g_red[(size_t)(b * 8 + g) * FW + j];
#pragma unroll
    for (int e2 = 0; e2 < 32; e2++)
        acc += ex[b * 32 + e2] * w[((size_t)KTOT + e2) * FW + j];
    float h = fmaxf(acc, 0.f);
    __shared__ float r0[512], r1[512];
    r0[j] = h * fc2w[j * 2 + 0];
    r1[j] = h * fc2w[j * 2 + 1];
    __syncthreads();
    for (int s = 256; s > 0; s >>= 1) {
        if (j < s) { r0[j] += r0[j + s]; r1[j] += r1[j + s]; }
        __syncthreads();
    }
    if (j == 0) {
        out[b * 2 + 0] = r0[0] + fc2b[0];
        out[b * 2 + 1] = r1[0] + fc2b[1];
    }
}

// ================= launch ==================================================
extern "C" void kernel_launch(void* const* d_in, const int* in_sizes, int n_in,
                              void* d_out, int out_size) {
    const float* inputs  = (const float*)d_in[0];
    const float* ex      = (const float*)d_in[1];
    const int*   erow    = (const int*)  d_in[2];
    const int*   ecol    = (const int*)  d_in[3];
    const float* eval    = (const float*)d_in[4];
    const float* W1      = (const float*)d_in[5];
    const float* b1      = (const float*)d_in[6];
    const float* g1      = (const float*)d_in[7];
    const float* be1     = (const float*)d_in[8];
    const float* W2      = (const float*)d_in[9];
    const float* b2      = (const float*)d_in[10];
    const float* g2      = (const float*)d_in[11];
    const float* be2     = (const float*)d_in[12];
    const float* fc1w    = (const float*)d_in[13];
    const float* fc1b    = (const float*)d_in[14];
    const float* fc2w    = (const float*)d_in[15];
    const float* fc2b    = (const float*)d_in[16];
    float* out = (float*)d_out;

    float* bufA; cudaGetSymbolAddress((void**)&bufA, g_bufA);
    float* bufB; cudaGetSymbolAddress((void**)&bufB, g_bufB);
    int* cnt;    cudaGetSymbolAddress((void**)&cnt,  g_count);

    cudaMemsetAsync(cnt, 0, MM * sizeof(int));
    k_hist<<<NNZ / 256, 256>>>(erow);
    k_scan<<<1, 1024>>>();
    k_scatter<<<NNZ / 256, 256>>>(erow, ecol, eval);

    k_lin1<<<(BSZ * MM) / 256, 256>>>(inputs, W1);          // bufA = X@W1   (m,b,c)
    k_spmm<<<MM, 128>>>(bufA, b1, bufB);                    // bufB = L@bufA + b1, stats
    k_bn<<<64, 256>>>(g1, be1);
    k_lin2<<<(BSZ * MM) / 256, 256>>>(bufB, W2, bufA);      // bufA = bnrelu(bufB)@W2
    k_spmm<<<MM, 128>>>(bufA, b2, bufB);                    // bufB = L@bufA + b2, stats
    k_bn<<<64, 256>>>(g2, be2);

    k_fc1<<<NKCH, 128>>>(fc1w, bufB);                       // split-K partials
    k_red1<<<BSZ * 8, 128>>>();                             // coalesced partial reduce
    k_red2<<<BSZ, 512>>>(fc1w, fc1b, ex, fc2w, fc2b, out);  // finish + fc2
}